// round 12
// baseline (speedup 1.0000x reference)
#include <cuda_runtime.h>
#include <cuda_bf16.h>

// Problem constants (fixed by dataset)
#define NSRC_MAX 10000
#define NDST_MAX 10000
#define EDGE_MAX 640000
#define SDIM 128
#define HNUM 4
#define DDIM 32

typedef unsigned long long u64;
typedef unsigned int u32;

// ---------------- device scratch (static, no allocs) ----------------
__device__ u32   g_ub[NSRC_MAX * (SDIM / 2)];   // x_src @ W_res^T as bf16x2 pairs
__device__ float g_v[NDST_MAX * SDIM];          // pred  @ W_res^T
__device__ float g_t1[NDST_MAX * SDIM];         // relu(x_dst @ W_pred1^T + b1)
__device__ float g_as[NSRC_MAX * HNUM];
__device__ float g_ad[NDST_MAX * HNUM];
__device__ float g_Msrc[SDIM * HNUM];
__device__ float g_Mdst[SDIM * HNUM];
__device__ float g_Wrv[SDIM * SDIM];            // W_res @ W_pred2
__device__ float g_brv[SDIM];                   // W_res @ b_pred2
__device__ int   g_cnt[NDST_MAX + 1];
__device__ int   g_off[NDST_MAX + 1];
__device__ int   g_cur[NDST_MAX];
__device__ int   g_csr_src[EDGE_MAX];

__device__ __forceinline__ float warp_sum(float v) {
    #pragma unroll
    for (int o = 16; o; o >>= 1) v += __shfl_xor_sync(0xffffffffu, v, o);
    return v;
}

// ---- f32x2 packed-math helpers (FFMA2: PTX-only, doubles fp32 FMA rate) ----
__device__ __forceinline__ u64 pack2(float x, float y) {
    u64 r;
    asm("mov.b64 %0, {%1, %2};" : "=l"(r)
        : "r"(__float_as_uint(x)), "r"(__float_as_uint(y)));
    return r;
}
__device__ __forceinline__ float2 unpack2(u64 v) {
    u32 lo, hi;
    asm("mov.b64 {%0, %1}, %2;" : "=r"(lo), "=r"(hi) : "l"(v));
    return make_float2(__uint_as_float(lo), __uint_as_float(hi));
}
__device__ __forceinline__ void fma2(u64& d, u64 a, u64 b) {
    asm("fma.rn.f32x2 %0, %1, %2, %3;" : "=l"(d) : "l"(a), "l"(b), "l"(d));
}
// pack (lo, hi) floats to bf16x2 (first PTX source -> upper half)
__device__ __forceinline__ u32 bf2(float lo, float hi) {
    u32 r;
    asm("cvt.rn.bf16x2.f32 %0, %1, %2;" : "=r"(r) : "f"(hi), "f"(lo));
    return r;
}

// ---------------- tiny precompute kernels ----------------
// Fold attention vectors into weights: M[s,h] = sum_d W[(h*32+d)*128 + s] * att[h*32+d]
__global__ void k_fold_att(const float* __restrict__ Wsrc, const float* __restrict__ attsrc,
                           const float* __restrict__ Wdst, const float* __restrict__ attdst) {
    int b = blockIdx.x;
    const float* W   = b ? Wdst   : Wsrc;
    const float* att = b ? attdst : attsrc;
    float* out       = b ? g_Mdst : g_Msrc;
    int t = threadIdx.x;
    if (t >= SDIM * HNUM) return;
    int s = t >> 2, h = t & 3;
    float acc = 0.f;
    #pragma unroll 8
    for (int d = 0; d < DDIM; d++)
        acc += W[(h * DDIM + d) * SDIM + s] * att[h * DDIM + d];
    out[s * 4 + h] = acc;
}

// W_rv[o,k] = sum_i W_res[o,i] * W_pred2[i,k];  b_rv[o] = sum_i W_res[o,i] * b_pred2[i]
__global__ void k_wrv(const float* __restrict__ Wres, const float* __restrict__ Wpred2,
                      const float* __restrict__ bpred2) {
    __shared__ float sh[SDIM];
    __shared__ float ws[4];
    int o = blockIdx.x, t = threadIdx.x;
    sh[t] = Wres[o * SDIM + t];
    __syncthreads();
    float s = 0.f;
    #pragma unroll 8
    for (int i = 0; i < SDIM; i++)
        s += sh[i] * Wpred2[i * SDIM + t];
    g_Wrv[o * SDIM + t] = s;
    float p = sh[t] * bpred2[t];
    p = warp_sum(p);
    if ((t & 31) == 0) ws[t >> 5] = p;
    __syncthreads();
    if (t == 0) g_brv[o] = ws[0] + ws[1] + ws[2] + ws[3];
}

// a[n,h] = sum_k x[n,k] * M[k,h]   (warp per row)
__global__ void k_logits(const float* __restrict__ xsrc, const float* __restrict__ xdst,
                         int Nsrc, int Ndst) {
    int y = blockIdx.y;
    const float* x  = y ? xdst   : xsrc;
    const float* Mw = y ? g_Mdst : g_Msrc;
    float* out      = y ? g_ad   : g_as;
    int N           = y ? Ndst   : Nsrc;
    int warp = threadIdx.x >> 5, lane = threadIdx.x & 31;
    int row = blockIdx.x * 8 + warp;
    if (row >= N) return;
    const float* xr = x + row * SDIM;
    float p0 = 0, p1 = 0, p2 = 0, p3 = 0;
    #pragma unroll
    for (int k = lane; k < SDIM; k += 32) {
        float xv = __ldg(&xr[k]);
        p0 += xv * Mw[k * 4 + 0];
        p1 += xv * Mw[k * 4 + 1];
        p2 += xv * Mw[k * 4 + 2];
        p3 += xv * Mw[k * 4 + 3];
    }
    p0 = warp_sum(p0); p1 = warp_sum(p1); p2 = warp_sum(p2); p3 = warp_sum(p3);
    if (lane == 0) {
        out[row * 4 + 0] = p0; out[row * 4 + 1] = p1;
        out[row * 4 + 2] = p2; out[row * 4 + 3] = p3;
    }
}

// ---------------- GEMM: C[M,128] = act(A[M,128] @ B[128,128]^T + bias) ----------------
// 128x128 tile, 256 threads, 8x8 per thread via f32x2 packed FMA.
// A tile stored pre-duplicated as u64 pairs -> no pack MOVs in the inner loop.
#define TM 128
#define TN 128
#define TK 16
__global__ __launch_bounds__(256) void k_gemm(
    const float* __restrict__ xsrc, const float* __restrict__ xdst,
    const float* __restrict__ Wres, const float* __restrict__ Wpred1,
    const float* __restrict__ bpred1, const float* __restrict__ Wself,
    const float* __restrict__ bself, float* __restrict__ dout,
    int Nsrc, int Ndst, int phase) {

    const float *A, *B, *bias;
    float* C = nullptr;
    int M;
    int doRelu = 0, toBf16 = 0;
    if (phase == 0) {
        int j = blockIdx.y;
        if (j == 0)      { A = xsrc; B = Wres;   bias = nullptr; M = Nsrc; toBf16 = 1; }
        else if (j == 1) { A = xdst; B = Wpred1; bias = bpred1;  C = g_t1; M = Ndst; doRelu = 1; }
        else             { A = xdst; B = Wself;  bias = bself;   C = dout; M = Ndst; }
    } else {
        A = g_t1; B = g_Wrv; bias = g_brv; C = g_v; M = Ndst;
    }

    __shared__ u64   As2[TK][TM + 2];
    __shared__ float Bs[TK][TN + 4];

    int tid = threadIdx.x;
    int tx = tid & 15, ty = tid >> 4;
    int row0 = blockIdx.x * TM;
    if (row0 >= M) return;

    u64 acc[8][4];
    #pragma unroll
    for (int r = 0; r < 8; r++)
        #pragma unroll
        for (int c = 0; c < 4; c++) acc[r][c] = 0ull;

    for (int k0 = 0; k0 < SDIM; k0 += TK) {
        // A tile: 128 rows x 16 k, stored duplicated (both f32x2 halves = value)
        #pragma unroll
        for (int i = 0; i < 2; i++) {
            int idx = tid + 256 * i;
            int r = idx >> 2, q = idx & 3;
            int grow = row0 + r;
            float4 vv = make_float4(0.f, 0.f, 0.f, 0.f);
            if (grow < M)
                vv = *reinterpret_cast<const float4*>(&A[grow * SDIM + k0 + q * 4]);
            As2[q * 4 + 0][r] = pack2(vv.x, vv.x);
            As2[q * 4 + 1][r] = pack2(vv.y, vv.y);
            As2[q * 4 + 2][r] = pack2(vv.z, vv.z);
            As2[q * 4 + 3][r] = pack2(vv.w, vv.w);
        }
        // B tile: 128 n x 16 k (pairs are natural: adjacent floats)
        #pragma unroll
        for (int i = 0; i < 2; i++) {
            int idx = tid + 256 * i;
            int n = idx >> 2, q = idx & 3;
            float4 vv = *reinterpret_cast<const float4*>(&B[n * SDIM + k0 + q * 4]);
            Bs[q * 4 + 0][n] = vv.x; Bs[q * 4 + 1][n] = vv.y;
            Bs[q * 4 + 2][n] = vv.z; Bs[q * 4 + 3][n] = vv.w;
        }
        __syncthreads();
        #pragma unroll
        for (int kk = 0; kk < TK; kk++) {
            const ulonglong2* apL = reinterpret_cast<const ulonglong2*>(&As2[kk][ty * 4]);
            const ulonglong2* apH = reinterpret_cast<const ulonglong2*>(&As2[kk][ty * 4 + 64]);
            ulonglong2 aL0 = apL[0], aL1 = apL[1];
            ulonglong2 aH0 = apH[0], aH1 = apH[1];
            u64 a2[8] = {aL0.x, aL0.y, aL1.x, aL1.y, aH0.x, aH0.y, aH1.x, aH1.y};
            const ulonglong2* bpL = reinterpret_cast<const ulonglong2*>(&Bs[kk][tx * 4]);
            const ulonglong2* bpH = reinterpret_cast<const ulonglong2*>(&Bs[kk][tx * 4 + 64]);
            ulonglong2 bL = bpL[0], bH = bpH[0];
            u64 b2[4] = {bL.x, bL.y, bH.x, bH.y};
            #pragma unroll
            for (int r = 0; r < 8; r++)
                #pragma unroll
                for (int c = 0; c < 4; c++)
                    fma2(acc[r][c], a2[r], b2[c]);
        }
        __syncthreads();
    }

    // epilogue: columns tx*4..tx*4+3 (lo) and 64+tx*4..+3 (hi)
    float4 bsL = make_float4(0.f, 0.f, 0.f, 0.f), bsH = bsL;
    if (bias) {
        bsL = *reinterpret_cast<const float4*>(&bias[tx * 4]);
        bsH = *reinterpret_cast<const float4*>(&bias[64 + tx * 4]);
    }
    #pragma unroll
    for (int r = 0; r < 8; r++) {
        int grow = row0 + ((r < 4) ? (ty * 4 + r) : (64 + ty * 4 + r - 4));
        if (grow >= M) continue;
        float2 p0 = unpack2(acc[r][0]), p1 = unpack2(acc[r][1]);
        float2 p2 = unpack2(acc[r][2]), p3 = unpack2(acc[r][3]);
        float4 lo = make_float4(p0.x + bsL.x, p0.y + bsL.y, p1.x + bsL.z, p1.y + bsL.w);
        float4 hi = make_float4(p2.x + bsH.x, p2.y + bsH.y, p3.x + bsH.z, p3.y + bsH.w);
        if (doRelu) {
            lo.x = fmaxf(lo.x, 0.f); lo.y = fmaxf(lo.y, 0.f);
            lo.z = fmaxf(lo.z, 0.f); lo.w = fmaxf(lo.w, 0.f);
            hi.x = fmaxf(hi.x, 0.f); hi.y = fmaxf(hi.y, 0.f);
            hi.z = fmaxf(hi.z, 0.f); hi.w = fmaxf(hi.w, 0.f);
        }
        if (toBf16) {
            uint2 uL = make_uint2(bf2(lo.x, lo.y), bf2(lo.z, lo.w));
            uint2 uH = make_uint2(bf2(hi.x, hi.y), bf2(hi.z, hi.w));
            *reinterpret_cast<uint2*>(&g_ub[grow * (SDIM / 2) + tx * 2]) = uL;
            *reinterpret_cast<uint2*>(&g_ub[grow * (SDIM / 2) + 32 + tx * 2]) = uH;
        } else {
            *reinterpret_cast<float4*>(&C[grow * SDIM + tx * 4]) = lo;
            *reinterpret_cast<float4*>(&C[grow * SDIM + 64 + tx * 4]) = hi;
        }
    }
}

// ---------------- CSR build (4 edges / thread for atomic-latency overlap) ----------------
__global__ void k_count(const int* __restrict__ edst, int E) {
    int i = blockIdx.x * blockDim.x + threadIdx.x;
    int n4 = E >> 2;
    if (i < n4) {
        int4 d = reinterpret_cast<const int4*>(edst)[i];
        atomicAdd(&g_cnt[d.x], 1);
        atomicAdd(&g_cnt[d.y], 1);
        atomicAdd(&g_cnt[d.z], 1);
        atomicAdd(&g_cnt[d.w], 1);
    } else if (i == n4) {
        for (int j = n4 * 4; j < E; j++) atomicAdd(&g_cnt[edst[j]], 1);
    }
}

__global__ void k_scan(int N) {
    __shared__ int sh[1024];
    int t = threadIdx.x;
    int per = (N + 1023) >> 10;
    int s = t * per, e = min(N, s + per);
    int tot = 0;
    for (int i = s; i < e; i++) tot += g_cnt[i];
    sh[t] = tot;
    __syncthreads();
    for (int o = 1; o < 1024; o <<= 1) {
        int v = (t >= o) ? sh[t - o] : 0;
        __syncthreads();
        sh[t] += v;
        __syncthreads();
    }
    int run = (t == 0) ? 0 : sh[t - 1];
    for (int i = s; i < e; i++) {
        g_off[i] = run;
        g_cur[i] = run;
        run += g_cnt[i];
    }
    if (t == 1023) g_off[N] = sh[1023];
}

__global__ void k_scatter(const int* __restrict__ esrc, const int* __restrict__ edst, int E) {
    int i = blockIdx.x * blockDim.x + threadIdx.x;
    int n4 = E >> 2;
    if (i < n4) {
        int4 d = reinterpret_cast<const int4*>(edst)[i];
        int4 s = reinterpret_cast<const int4*>(esrc)[i];
        int p0 = atomicAdd(&g_cur[d.x], 1);
        int p1 = atomicAdd(&g_cur[d.y], 1);
        int p2 = atomicAdd(&g_cur[d.z], 1);
        int p3 = atomicAdd(&g_cur[d.w], 1);
        g_csr_src[p0] = s.x;
        g_csr_src[p1] = s.y;
        g_csr_src[p2] = s.z;
        g_csr_src[p3] = s.w;
    } else if (i == n4) {
        for (int j = n4 * 4; j < E; j++) {
            int p = atomicAdd(&g_cur[edst[j]], 1);
            g_csr_src[p] = esrc[j];
        }
    }
}

// ---------------- edge aggregation: one block (128 thr) per dst node ----------------
// pass 2 uses LDG.128 (uint4 = 8 bf16 channels per thread) to cut load-instr count 4x.
#define CAP 512
__global__ __launch_bounds__(128) void k_edge(float* __restrict__ dout) {
    __shared__ int    sh_src[CAP];
    __shared__ float  sh_ex[4][CAP];
    __shared__ float  sh_denom[4];
    __shared__ float  red[8][SDIM + 4];

    int d = blockIdx.x;
    int t = threadIdx.x;
    int start = g_off[d], end = g_off[d + 1];
    int n = end - start;

    // pass 1: warp h1 computes exp-weights for head h1; warp 0 also caches src ids
    int h1 = t >> 5, lane = t & 31;
    float adh1 = g_ad[d * 4 + h1];
    float part = 0.f;
    for (int i = lane; i < n; i += 32) {
        int src = g_csr_src[start + i];
        if (h1 == 0 && i < CAP) sh_src[i] = src;
        float z = g_as[src * 4 + h1] + adh1;
        z = fmaxf(z, 0.f) + 0.2f * fminf(z, 0.f);   // leaky_relu 0.2
        float ex = __expf(z);                        // softmax shift-invariant: skip amax
        if (i < CAP) sh_ex[h1][i] = ex;
        part += ex;
    }
    part = warp_sum(part);
    if (lane == 0) sh_denom[h1] = part;
    __syncthreads();

    // pass 2: 16 channel-groups (8 ch each) x 8 edge-slots; uint4 (16B) u loads
    int p = t & 15, slot = t >> 4;
    int h2 = p >> 2;                      // head of channels 8p..8p+7
    float acc[8];
    #pragma unroll
    for (int j = 0; j < 8; j++) acc[j] = 0.f;

    int ncap = n < CAP ? n : CAP;
    #pragma unroll 4
    for (int i = slot; i < ncap; i += 8) {
        int src = sh_src[i];
        float w = sh_ex[h2][i];
        uint4 uv = __ldg(reinterpret_cast<const uint4*>(&g_ub[src * (SDIM / 2) + p * 4]));
        acc[0] += w * __uint_as_float(uv.x << 16);
        acc[1] += w * __uint_as_float(uv.x & 0xffff0000u);
        acc[2] += w * __uint_as_float(uv.y << 16);
        acc[3] += w * __uint_as_float(uv.y & 0xffff0000u);
        acc[4] += w * __uint_as_float(uv.z << 16);
        acc[5] += w * __uint_as_float(uv.z & 0xffff0000u);
        acc[6] += w * __uint_as_float(uv.w << 16);
        acc[7] += w * __uint_as_float(uv.w & 0xffff0000u);
    }
    // overflow path (n > CAP): recompute weights on the fly (rare/never for this data)
    if (n > CAP) {
        float adh2 = g_ad[d * 4 + h2];
        for (int j = CAP + slot; j < n; j += 8) {
            int src = g_csr_src[start + j];
            float z = g_as[src * 4 + h2] + adh2;
            z = fmaxf(z, 0.f) + 0.2f * fminf(z, 0.f);
            float w = __expf(z);
            uint4 uv = __ldg(reinterpret_cast<const uint4*>(&g_ub[src * (SDIM / 2) + p * 4]));
            acc[0] += w * __uint_as_float(uv.x << 16);
            acc[1] += w * __uint_as_float(uv.x & 0xffff0000u);
            acc[2] += w * __uint_as_float(uv.y << 16);
            acc[3] += w * __uint_as_float(uv.y & 0xffff0000u);
            acc[4] += w * __uint_as_float(uv.z << 16);
            acc[5] += w * __uint_as_float(uv.z & 0xffff0000u);
            acc[6] += w * __uint_as_float(uv.w << 16);
            acc[7] += w * __uint_as_float(uv.w & 0xffff0000u);
        }
    }
    #pragma unroll
    for (int j = 0; j < 8; j++) red[slot][p * 8 + j] = acc[j];
    __syncthreads();

    // final: thread t owns channel c=t; sum 8 slots, apply softmax norm + v correction
    int c = t;
    float a = 0.f;
    #pragma unroll
    for (int s = 0; s < 8; s++) a += red[s][c];
    float denom = sh_denom[c >> 5];
    float inv = 1.f / (denom + 1e-16f);
    float sumw = denom * inv;
    dout[d * SDIM + c] = dout[d * SDIM + c] + a * inv - g_v[d * SDIM + c] * sumw;
}

// ---------------- launch: R3 topology; wrv moved to side stream B ----------------
extern "C" void kernel_launch(void* const* d_in, const int* in_sizes, int n_in,
                              void* d_out, int out_size) {
    const float* x_src   = (const float*)d_in[0];
    const float* x_dst   = (const float*)d_in[1];
    const float* W_pred1 = (const float*)d_in[2];
    const float* b_pred1 = (const float*)d_in[3];
    const float* W_pred2 = (const float*)d_in[4];
    const float* b_pred2 = (const float*)d_in[5];
    const float* W_res   = (const float*)d_in[6];
    const float* W_src   = (const float*)d_in[7];
    const float* W_dst   = (const float*)d_in[8];
    const float* att_src = (const float*)d_in[9];
    const float* att_dst = (const float*)d_in[10];
    const float* W_self  = (const float*)d_in[11];
    const float* b_self  = (const float*)d_in[12];
    const int*   e_src   = (const int*)d_in[13];
    const int*   e_dst   = (const int*)d_in[14];
    float* out = (float*)d_out;

    int Nsrc = in_sizes[0] / SDIM;
    int Ndst = in_sizes[1] / SDIM;
    int E    = in_sizes[13];
    int maxN = Nsrc > Ndst ? Nsrc : Ndst;

    void* cnt_ptr = nullptr;
    cudaGetSymbolAddress(&cnt_ptr, g_cnt);

    cudaStream_t sA, sB;
    cudaStreamCreateWithFlags(&sA, cudaStreamNonBlocking);
    cudaStreamCreateWithFlags(&sB, cudaStreamNonBlocking);
    cudaEvent_t eF, eA, eB, eW;
    cudaEventCreateWithFlags(&eF, cudaEventDisableTiming);
    cudaEventCreateWithFlags(&eA, cudaEventDisableTiming);
    cudaEventCreateWithFlags(&eB, cudaEventDisableTiming);
    cudaEventCreateWithFlags(&eW, cudaEventDisableTiming);

    // fork from the (captured) main stream
    cudaEventRecord(eF, 0);
    cudaStreamWaitEvent(sA, eF, 0);
    cudaStreamWaitEvent(sB, eF, 0);

    int n4 = E >> 2;
    int csrGrid = (n4 + 1 + 255) / 256;

    // track A: CSR build (independent of all GEMMs)
    cudaMemsetAsync(cnt_ptr, 0, (Ndst + 1) * sizeof(int), sA);
    k_count<<<csrGrid, 256, 0, sA>>>(e_dst, E);
    k_scan<<<1, 1024, 0, sA>>>(Ndst);
    k_scatter<<<csrGrid, 256, 0, sA>>>(e_src, e_dst, E);

    // track B: wrv first (gemm1 gates on it; slack = gemm0 duration), then logits
    k_wrv<<<SDIM, SDIM, 0, sB>>>(W_res, W_pred2, b_pred2);
    cudaEventRecord(eW, sB);
    k_fold_att<<<2, 512, 0, sB>>>(W_src, att_src, W_dst, att_dst);
    dim3 gl((maxN + 7) / 8, 2);
    k_logits<<<gl, 256, 0, sB>>>(x_src, x_dst, Nsrc, Ndst);

    // main: GEMM chain (fused phase-0 fills the chip in one launch)
    dim3 g0((maxN + TM - 1) / TM, 3);
    k_gemm<<<g0, 256>>>(x_src, x_dst, W_res, W_pred1, b_pred1, W_self, b_self,
                        out, Nsrc, Ndst, 0);
    cudaStreamWaitEvent(0, eW, 0);
    dim3 g1((Ndst + TM - 1) / TM, 1);
    k_gemm<<<g1, 256>>>(x_src, x_dst, W_res, W_pred1, b_pred1, W_self, b_self,
                        out, Nsrc, Ndst, 1);

    // join side tracks back into the main stream
    cudaEventRecord(eA, sA);
    cudaEventRecord(eB, sB);
    cudaStreamWaitEvent(0, eA, 0);
    cudaStreamWaitEvent(0, eB, 0);

    k_edge<<<Ndst, 128>>>(out);

    cudaEventDestroy(eF);
    cudaEventDestroy(eA);
    cudaEventDestroy(eB);
    cudaEventDestroy(eW);
    cudaStreamDestroy(sA);
    cudaStreamDestroy(sB);
}

// round 13
// speedup vs baseline: 1.0928x; 1.0928x over previous
#include <cuda_runtime.h>
#include <cuda_bf16.h>

// Problem constants (fixed by dataset)
#define NSRC_MAX 10000
#define NDST_MAX 10000
#define EDGE_MAX 640000
#define SDIM 128
#define HNUM 4
#define DDIM 32

typedef unsigned long long u64;
typedef unsigned int u32;

// ---------------- device scratch (static, no allocs) ----------------
__device__ u32   g_ub[NSRC_MAX * (SDIM / 2)];   // x_src @ W_res^T as bf16x2 pairs
__device__ float g_v[NDST_MAX * SDIM];          // pred  @ W_res^T
__device__ float g_t1[NDST_MAX * SDIM];         // relu(x_dst @ W_pred1^T + b1)
__device__ float g_as[NSRC_MAX * HNUM];
__device__ float g_ad[NDST_MAX * HNUM];
__device__ float g_Msrc[SDIM * HNUM];
__device__ float g_Mdst[SDIM * HNUM];
__device__ float g_Wrv[SDIM * SDIM];            // W_res @ W_pred2
__device__ float g_brv[SDIM];                   // W_res @ b_pred2
__device__ int   g_cnt[NDST_MAX + 1];
__device__ int   g_off[NDST_MAX + 1];
__device__ int   g_cur[NDST_MAX];
__device__ int   g_csr_src[EDGE_MAX];

__device__ __forceinline__ float warp_sum(float v) {
    #pragma unroll
    for (int o = 16; o; o >>= 1) v += __shfl_xor_sync(0xffffffffu, v, o);
    return v;
}

// ---- f32x2 packed-math helpers (FFMA2: PTX-only, doubles fp32 FMA rate) ----
__device__ __forceinline__ u64 pack2(float x, float y) {
    u64 r;
    asm("mov.b64 %0, {%1, %2};" : "=l"(r)
        : "r"(__float_as_uint(x)), "r"(__float_as_uint(y)));
    return r;
}
__device__ __forceinline__ float2 unpack2(u64 v) {
    u32 lo, hi;
    asm("mov.b64 {%0, %1}, %2;" : "=r"(lo), "=r"(hi) : "l"(v));
    return make_float2(__uint_as_float(lo), __uint_as_float(hi));
}
__device__ __forceinline__ void fma2(u64& d, u64 a, u64 b) {
    asm("fma.rn.f32x2 %0, %1, %2, %3;" : "=l"(d) : "l"(a), "l"(b), "l"(d));
}
// pack (lo, hi) floats to bf16x2 (first PTX source -> upper half)
__device__ __forceinline__ u32 bf2(float lo, float hi) {
    u32 r;
    asm("cvt.rn.bf16x2.f32 %0, %1, %2;" : "=r"(r) : "f"(hi), "f"(lo));
    return r;
}

#define TM 128
#define TN 128
#define TK 16

// ---------------- GEMM body (R11-proven): C[M,128]=act(A@B^T+bias) ----------------
__device__ void gemm_body(const float* __restrict__ A, const float* __restrict__ B,
                          const float* __restrict__ bias, float* __restrict__ C,
                          int M, int bx, int doRelu, int toBf16,
                          float (*As)[TM + 4], float (*Bs)[TN + 4]) {
    int tid = threadIdx.x;
    int tx = tid & 15, ty = tid >> 4;
    int row0 = bx * TM;
    if (row0 >= M) return;

    u64 acc[8][4];
    #pragma unroll
    for (int r = 0; r < 8; r++)
        #pragma unroll
        for (int c = 0; c < 4; c++) acc[r][c] = 0ull;

    for (int k0 = 0; k0 < SDIM; k0 += TK) {
        #pragma unroll
        for (int i = 0; i < 2; i++) {
            int idx = tid + 256 * i;
            int r = idx >> 2, q = idx & 3;
            int grow = row0 + r;
            float4 vv = make_float4(0.f, 0.f, 0.f, 0.f);
            if (grow < M)
                vv = *reinterpret_cast<const float4*>(&A[grow * SDIM + k0 + q * 4]);
            As[q * 4 + 0][r] = vv.x; As[q * 4 + 1][r] = vv.y;
            As[q * 4 + 2][r] = vv.z; As[q * 4 + 3][r] = vv.w;
        }
        #pragma unroll
        for (int i = 0; i < 2; i++) {
            int idx = tid + 256 * i;
            int n = idx >> 2, q = idx & 3;
            float4 vv = *reinterpret_cast<const float4*>(&B[n * SDIM + k0 + q * 4]);
            Bs[q * 4 + 0][n] = vv.x; Bs[q * 4 + 1][n] = vv.y;
            Bs[q * 4 + 2][n] = vv.z; Bs[q * 4 + 3][n] = vv.w;
        }
        __syncthreads();
        #pragma unroll
        for (int kk = 0; kk < TK; kk++) {
            float4 aL = *reinterpret_cast<const float4*>(&As[kk][ty * 4]);
            float4 aH = *reinterpret_cast<const float4*>(&As[kk][ty * 4 + 64]);
            float4 bL = *reinterpret_cast<const float4*>(&Bs[kk][tx * 4]);
            float4 bH = *reinterpret_cast<const float4*>(&Bs[kk][tx * 4 + 64]);
            u64 a2[8];
            a2[0] = pack2(aL.x, aL.x); a2[1] = pack2(aL.y, aL.y);
            a2[2] = pack2(aL.z, aL.z); a2[3] = pack2(aL.w, aL.w);
            a2[4] = pack2(aH.x, aH.x); a2[5] = pack2(aH.y, aH.y);
            a2[6] = pack2(aH.z, aH.z); a2[7] = pack2(aH.w, aH.w);
            u64 b2[4];
            b2[0] = pack2(bL.x, bL.y); b2[1] = pack2(bL.z, bL.w);
            b2[2] = pack2(bH.x, bH.y); b2[3] = pack2(bH.z, bH.w);
            #pragma unroll
            for (int r = 0; r < 8; r++)
                #pragma unroll
                for (int c = 0; c < 4; c++)
                    fma2(acc[r][c], a2[r], b2[c]);
        }
        __syncthreads();
    }

    float4 bsL = make_float4(0.f, 0.f, 0.f, 0.f), bsH = bsL;
    if (bias) {
        bsL = *reinterpret_cast<const float4*>(&bias[tx * 4]);
        bsH = *reinterpret_cast<const float4*>(&bias[64 + tx * 4]);
    }
    #pragma unroll
    for (int r = 0; r < 8; r++) {
        int grow = row0 + ((r < 4) ? (ty * 4 + r) : (64 + ty * 4 + r - 4));
        if (grow >= M) continue;
        float2 p0 = unpack2(acc[r][0]), p1 = unpack2(acc[r][1]);
        float2 p2 = unpack2(acc[r][2]), p3 = unpack2(acc[r][3]);
        float4 lo = make_float4(p0.x + bsL.x, p0.y + bsL.y, p1.x + bsL.z, p1.y + bsL.w);
        float4 hi = make_float4(p2.x + bsH.x, p2.y + bsH.y, p3.x + bsH.z, p3.y + bsH.w);
        if (doRelu) {
            lo.x = fmaxf(lo.x, 0.f); lo.y = fmaxf(lo.y, 0.f);
            lo.z = fmaxf(lo.z, 0.f); lo.w = fmaxf(lo.w, 0.f);
            hi.x = fmaxf(hi.x, 0.f); hi.y = fmaxf(hi.y, 0.f);
            hi.z = fmaxf(hi.z, 0.f); hi.w = fmaxf(hi.w, 0.f);
        }
        if (toBf16) {
            uint2 uL = make_uint2(bf2(lo.x, lo.y), bf2(lo.z, lo.w));
            uint2 uH = make_uint2(bf2(hi.x, hi.y), bf2(hi.z, hi.w));
            *reinterpret_cast<uint2*>(&g_ub[grow * (SDIM / 2) + tx * 2]) = uL;
            *reinterpret_cast<uint2*>(&g_ub[grow * (SDIM / 2) + 32 + tx * 2]) = uH;
        } else {
            *reinterpret_cast<float4*>(&C[grow * SDIM + tx * 4]) = lo;
            *reinterpret_cast<float4*>(&C[grow * SDIM + 64 + tx * 4]) = hi;
        }
    }
}

// ---------------- MEGA1: wrv | fold_att | 3 GEMMs | count | logits ----------------
__global__ __launch_bounds__(256) void k_mega1(
    const float* __restrict__ xsrc, const float* __restrict__ xdst,
    const float* __restrict__ Wres, const float* __restrict__ Wpred1,
    const float* __restrict__ bpred1, const float* __restrict__ Wpred2,
    const float* __restrict__ bpred2, const float* __restrict__ Wself,
    const float* __restrict__ bself,
    const float* __restrict__ Wsrc, const float* __restrict__ attsrc,
    const float* __restrict__ Wdst, const float* __restrict__ attdst,
    const int* __restrict__ edst,
    float* __restrict__ dout,
    int Nsrc, int Ndst, int E, int nbg, int ncnt, int nrow8) {

    __shared__ float As[TK][TM + 4];
    __shared__ float Bs[TK][TN + 4];
    __shared__ float ws[4];

    int b = blockIdx.x;
    int t = threadIdx.x;

    // layout: [wrv 128][fold 4][gemm 3*nbg][count ncnt][logits 2*nrow8]
    if (b < SDIM) {
        // ---- wrv: one output row o = b ----
        int o = b;
        float* sh = &As[0][0];  // 128 floats
        if (t < SDIM) sh[t] = Wres[o * SDIM + t];
        __syncthreads();
        if (t < SDIM) {
            float s = 0.f;
            #pragma unroll 8
            for (int i = 0; i < SDIM; i++)
                s += sh[i] * Wpred2[i * SDIM + t];
            g_Wrv[o * SDIM + t] = s;
            float p = sh[t] * bpred2[t];
            p = warp_sum(p);
            if ((t & 31) == 0) ws[t >> 5] = p;
        }
        __syncthreads();
        if (t == 0) g_brv[o] = ws[0] + ws[1] + ws[2] + ws[3];
        return;
    }
    b -= SDIM;
    if (b < 4) {
        // ---- fold_att: sub = b; side = sub>>1; half = sub&1 ----
        int side = b >> 1;
        const float* W   = side ? Wdst   : Wsrc;
        const float* att = side ? attdst : attsrc;
        float* out       = side ? g_Mdst : g_Msrc;
        int t2 = (b & 1) * 256 + t;          // 0..511
        int s = t2 >> 2, h = t2 & 3;
        float acc = 0.f;
        #pragma unroll 8
        for (int d = 0; d < DDIM; d++)
            acc += W[(h * DDIM + d) * SDIM + s] * att[h * DDIM + d];
        out[s * 4 + h] = acc;
        return;
    }
    b -= 4;
    if (b < 3 * nbg) {
        int j = b / nbg, bx = b % nbg;
        if (j == 0)      gemm_body(xsrc, Wres,   nullptr, nullptr, Nsrc, bx, 0, 1, As, Bs);
        else if (j == 1) gemm_body(xdst, Wpred1, bpred1,  g_t1,    Ndst, bx, 1, 0, As, Bs);
        else             gemm_body(xdst, Wself,  bself,   dout,    Ndst, bx, 0, 0, As, Bs);
        return;
    }
    b -= 3 * nbg;
    if (b < ncnt) {
        // ---- count: 4 edges per thread ----
        int i = b * 256 + t;
        int n4 = E >> 2;
        if (i < n4) {
            int4 d = reinterpret_cast<const int4*>(edst)[i];
            atomicAdd(&g_cnt[d.x], 1);
            atomicAdd(&g_cnt[d.y], 1);
            atomicAdd(&g_cnt[d.z], 1);
            atomicAdd(&g_cnt[d.w], 1);
        } else if (i == n4) {
            for (int j = n4 * 4; j < E; j++) atomicAdd(&g_cnt[edst[j]], 1);
        }
        return;
    }
    b -= ncnt;
    {
        // ---- logits: 8 rows per block (warp per row) ----
        int y = b / nrow8;
        int bx = b % nrow8;
        const float* x  = y ? xdst   : xsrc;
        const float* Mw = y ? g_Mdst : g_Msrc;
        float* out      = y ? g_ad   : g_as;
        int N           = y ? Ndst   : Nsrc;
        int warp = t >> 5, lane = t & 31;
        int row = bx * 8 + warp;
        if (row >= N) return;
        const float* xr = x + row * SDIM;
        float p0 = 0, p1 = 0, p2 = 0, p3 = 0;
        #pragma unroll
        for (int k = lane; k < SDIM; k += 32) {
            float xv = __ldg(&xr[k]);
            p0 += xv * Mw[k * 4 + 0];
            p1 += xv * Mw[k * 4 + 1];
            p2 += xv * Mw[k * 4 + 2];
            p3 += xv * Mw[k * 4 + 3];
        }
        p0 = warp_sum(p0); p1 = warp_sum(p1); p2 = warp_sum(p2); p3 = warp_sum(p3);
        if (lane == 0) {
            out[row * 4 + 0] = p0; out[row * 4 + 1] = p1;
            out[row * 4 + 2] = p2; out[row * 4 + 3] = p3;
        }
    }
}

// ---------------- scan (prefix over degree counts) ----------------
__global__ void k_scan(int N) {
    __shared__ int sh[1024];
    int t = threadIdx.x;
    int per = (N + 1023) >> 10;
    int s = t * per, e = min(N, s + per);
    int tot = 0;
    for (int i = s; i < e; i++) tot += g_cnt[i];
    sh[t] = tot;
    __syncthreads();
    for (int o = 1; o < 1024; o <<= 1) {
        int v = (t >= o) ? sh[t - o] : 0;
        __syncthreads();
        sh[t] += v;
        __syncthreads();
    }
    int run = (t == 0) ? 0 : sh[t - 1];
    for (int i = s; i < e; i++) {
        g_off[i] = run;
        g_cur[i] = run;
        run += g_cnt[i];
    }
    if (t == 1023) g_off[N] = sh[1023];
}

// ---------------- MEGA2: v-GEMM | scatter ----------------
__global__ __launch_bounds__(256) void k_mega2(
    const int* __restrict__ esrc, const int* __restrict__ edst,
    int Ndst, int E, int nbg2, int ncnt) {

    __shared__ float As[TK][TM + 4];
    __shared__ float Bs[TK][TN + 4];

    int b = blockIdx.x;
    int t = threadIdx.x;
    if (b < nbg2) {
        gemm_body(g_t1, g_Wrv, g_brv, g_v, Ndst, b, 0, 0, As, Bs);
        return;
    }
    b -= nbg2;
    {
        int i = b * 256 + t;
        int n4 = E >> 2;
        if (i < n4) {
            int4 d = reinterpret_cast<const int4*>(edst)[i];
            int4 s = reinterpret_cast<const int4*>(esrc)[i];
            int p0 = atomicAdd(&g_cur[d.x], 1);
            int p1 = atomicAdd(&g_cur[d.y], 1);
            int p2 = atomicAdd(&g_cur[d.z], 1);
            int p3 = atomicAdd(&g_cur[d.w], 1);
            g_csr_src[p0] = s.x;
            g_csr_src[p1] = s.y;
            g_csr_src[p2] = s.z;
            g_csr_src[p3] = s.w;
        } else if (i == n4) {
            for (int j = n4 * 4; j < E; j++) {
                int p = atomicAdd(&g_cur[edst[j]], 1);
                g_csr_src[p] = esrc[j];
            }
        }
    }
}

// ---------------- edge aggregation: one block (128 thr) per dst node ----------------
// pass 2 uses LDG.128 (uint4 = 8 bf16 channels per thread) to cut load-instr count 4x.
#define CAP 512
__global__ __launch_bounds__(128) void k_edge(float* __restrict__ dout) {
    __shared__ int    sh_src[CAP];
    __shared__ float  sh_ex[4][CAP];
    __shared__ float  sh_denom[4];
    __shared__ float  red[8][SDIM + 4];

    int d = blockIdx.x;
    int t = threadIdx.x;
    int start = g_off[d], end = g_off[d + 1];
    int n = end - start;

    // pass 1: warp h1 computes exp-weights for head h1; warp 0 also caches src ids
    int h1 = t >> 5, lane = t & 31;
    float adh1 = g_ad[d * 4 + h1];
    float part = 0.f;
    for (int i = lane; i < n; i += 32) {
        int src = g_csr_src[start + i];
        if (h1 == 0 && i < CAP) sh_src[i] = src;
        float z = g_as[src * 4 + h1] + adh1;
        z = fmaxf(z, 0.f) + 0.2f * fminf(z, 0.f);   // leaky_relu 0.2
        float ex = __expf(z);                        // softmax shift-invariant: skip amax
        if (i < CAP) sh_ex[h1][i] = ex;
        part += ex;
    }
    part = warp_sum(part);
    if (lane == 0) sh_denom[h1] = part;
    __syncthreads();

    // pass 2: 16 channel-groups (8 ch each) x 8 edge-slots; uint4 (16B) u loads
    int p = t & 15, slot = t >> 4;
    int h2 = p >> 2;
    float acc[8];
    #pragma unroll
    for (int j = 0; j < 8; j++) acc[j] = 0.f;

    int ncap = n < CAP ? n : CAP;
    #pragma unroll 4
    for (int i = slot; i < ncap; i += 8) {
        int src = sh_src[i];
        float w = sh_ex[h2][i];
        uint4 uv = __ldg(reinterpret_cast<const uint4*>(&g_ub[src * (SDIM / 2) + p * 4]));
        acc[0] += w * __uint_as_float(uv.x << 16);
        acc[1] += w * __uint_as_float(uv.x & 0xffff0000u);
        acc[2] += w * __uint_as_float(uv.y << 16);
        acc[3] += w * __uint_as_float(uv.y & 0xffff0000u);
        acc[4] += w * __uint_as_float(uv.z << 16);
        acc[5] += w * __uint_as_float(uv.z & 0xffff0000u);
        acc[6] += w * __uint_as_float(uv.w << 16);
        acc[7] += w * __uint_as_float(uv.w & 0xffff0000u);
    }
    if (n > CAP) {
        float adh2 = g_ad[d * 4 + h2];
        for (int j = CAP + slot; j < n; j += 8) {
            int src = g_csr_src[start + j];
            float z = g_as[src * 4 + h2] + adh2;
            z = fmaxf(z, 0.f) + 0.2f * fminf(z, 0.f);
            float w = __expf(z);
            uint4 uv = __ldg(reinterpret_cast<const uint4*>(&g_ub[src * (SDIM / 2) + p * 4]));
            acc[0] += w * __uint_as_float(uv.x << 16);
            acc[1] += w * __uint_as_float(uv.x & 0xffff0000u);
            acc[2] += w * __uint_as_float(uv.y << 16);
            acc[3] += w * __uint_as_float(uv.y & 0xffff0000u);
            acc[4] += w * __uint_as_float(uv.z << 16);
            acc[5] += w * __uint_as_float(uv.z & 0xffff0000u);
            acc[6] += w * __uint_as_float(uv.w << 16);
            acc[7] += w * __uint_as_float(uv.w & 0xffff0000u);
        }
    }
    #pragma unroll
    for (int j = 0; j < 8; j++) red[slot][p * 8 + j] = acc[j];
    __syncthreads();

    // final: thread t owns channel c=t
    int c = t;
    float a = 0.f;
    #pragma unroll
    for (int s = 0; s < 8; s++) a += red[s][c];
    float denom = sh_denom[c >> 5];
    float inv = 1.f / (denom + 1e-16f);
    float sumw = denom * inv;
    dout[d * SDIM + c] = dout[d * SDIM + c] + a * inv - g_v[d * SDIM + c] * sumw;
}

// ---------------- launch: 5-node single-stream chain ----------------
extern "C" void kernel_launch(void* const* d_in, const int* in_sizes, int n_in,
                              void* d_out, int out_size) {
    const float* x_src   = (const float*)d_in[0];
    const float* x_dst   = (const float*)d_in[1];
    const float* W_pred1 = (const float*)d_in[2];
    const float* b_pred1 = (const float*)d_in[3];
    const float* W_pred2 = (const float*)d_in[4];
    const float* b_pred2 = (const float*)d_in[5];
    const float* W_res   = (const float*)d_in[6];
    const float* W_src   = (const float*)d_in[7];
    const float* W_dst   = (const float*)d_in[8];
    const float* att_src = (const float*)d_in[9];
    const float* att_dst = (const float*)d_in[10];
    const float* W_self  = (const float*)d_in[11];
    const float* b_self  = (const float*)d_in[12];
    const int*   e_src   = (const int*)d_in[13];
    const int*   e_dst   = (const int*)d_in[14];
    float* out = (float*)d_out;

    int Nsrc = in_sizes[0] / SDIM;
    int Ndst = in_sizes[1] / SDIM;
    int E    = in_sizes[13];
    int maxN = Nsrc > Ndst ? Nsrc : Ndst;

    void* cnt_ptr = nullptr;
    cudaGetSymbolAddress(&cnt_ptr, g_cnt);

    int nbg   = (maxN + TM - 1) / TM;
    int nbg2  = (Ndst + TM - 1) / TM;
    int n4    = E >> 2;
    int ncnt  = (n4 + 1 + 255) / 256;
    int nrow8 = (maxN + 7) / 8;
    int grid1 = SDIM + 4 + 3 * nbg + ncnt + 2 * nrow8;
    int grid2 = nbg2 + ncnt;

    cudaMemsetAsync(cnt_ptr, 0, (Ndst + 1) * sizeof(int), 0);
    k_mega1<<<grid1, 256>>>(x_src, x_dst, W_res, W_pred1, b_pred1, W_pred2, b_pred2,
                            W_self, b_self, W_src, att_src, W_dst, att_dst,
                            e_dst, out, Nsrc, Ndst, E, nbg, ncnt, nrow8);
    k_scan<<<1, 1024>>>(Ndst);
    k_mega2<<<grid2, 256>>>(e_src, e_dst, Ndst, E, nbg2, ncnt);
    k_edge<<<Ndst, 128>>>(out);
}

// round 14
// speedup vs baseline: 1.0963x; 1.0032x over previous
#include <cuda_runtime.h>
#include <cuda_bf16.h>

// Problem constants (fixed by dataset)
#define NSRC_MAX 10000
#define NDST_MAX 10000
#define EDGE_MAX 640000
#define SDIM 128
#define HNUM 4
#define DDIM 32

typedef unsigned long long u64;
typedef unsigned int u32;

// ---------------- device scratch (static, no allocs) ----------------
__device__ u32    g_ub[NSRC_MAX * (SDIM / 2)];  // x_src @ W_res^T as bf16x2 pairs
__device__ float  g_v[NDST_MAX * SDIM];         // pred  @ W_res^T
__device__ float  g_t1[NDST_MAX * SDIM];        // relu(x_dst @ W_pred1^T + b1)
__device__ float4 g_as4[NSRC_MAX];              // per-src logits, 4 heads packed
__device__ float4 g_ad4[NDST_MAX];              // per-dst logits, 4 heads packed
__device__ float  g_Msrc[SDIM * HNUM];
__device__ float  g_Mdst[SDIM * HNUM];
__device__ float  g_Wrv[SDIM * SDIM];           // W_res @ W_pred2
__device__ float  g_brv[SDIM];                  // W_res @ b_pred2
__device__ int    g_cnt[NDST_MAX + 1];
__device__ int    g_off[NDST_MAX + 1];
__device__ int    g_cur[NDST_MAX];
__device__ int    g_csr_src[EDGE_MAX];

__device__ __forceinline__ float warp_sum(float v) {
    #pragma unroll
    for (int o = 16; o; o >>= 1) v += __shfl_xor_sync(0xffffffffu, v, o);
    return v;
}

// ---- f32x2 packed-math helpers (FFMA2: PTX-only, doubles fp32 FMA rate) ----
__device__ __forceinline__ u64 pack2(float x, float y) {
    u64 r;
    asm("mov.b64 %0, {%1, %2};" : "=l"(r)
        : "r"(__float_as_uint(x)), "r"(__float_as_uint(y)));
    return r;
}
__device__ __forceinline__ float2 unpack2(u64 v) {
    u32 lo, hi;
    asm("mov.b64 {%0, %1}, %2;" : "=r"(lo), "=r"(hi) : "l"(v));
    return make_float2(__uint_as_float(lo), __uint_as_float(hi));
}
__device__ __forceinline__ void fma2(u64& d, u64 a, u64 b) {
    asm("fma.rn.f32x2 %0, %1, %2, %3;" : "=l"(d) : "l"(a), "l"(b), "l"(d));
}
// pack (lo, hi) floats to bf16x2 (first PTX source -> upper half)
__device__ __forceinline__ u32 bf2(float lo, float hi) {
    u32 r;
    asm("cvt.rn.bf16x2.f32 %0, %1, %2;" : "=r"(r) : "f"(hi), "f"(lo));
    return r;
}
__device__ __forceinline__ float lrelu_exp(float z) {
    z = fmaxf(z, 0.f) + 0.2f * fminf(z, 0.f);   // leaky_relu 0.2
    return __expf(z);                            // softmax shift-invariant: skip amax
}

#define TM 128
#define TN 128
#define TK 16

// ---------------- GEMM body (R11-proven): C[M,128]=act(A@B^T+bias) ----------------
__device__ void gemm_body(const float* __restrict__ A, const float* __restrict__ B,
                          const float* __restrict__ bias, float* __restrict__ C,
                          int M, int bx, int doRelu, int toBf16,
                          float (*As)[TM + 4], float (*Bs)[TN + 4]) {
    int tid = threadIdx.x;
    int tx = tid & 15, ty = tid >> 4;
    int row0 = bx * TM;
    if (row0 >= M) return;

    u64 acc[8][4];
    #pragma unroll
    for (int r = 0; r < 8; r++)
        #pragma unroll
        for (int c = 0; c < 4; c++) acc[r][c] = 0ull;

    for (int k0 = 0; k0 < SDIM; k0 += TK) {
        #pragma unroll
        for (int i = 0; i < 2; i++) {
            int idx = tid + 256 * i;
            int r = idx >> 2, q = idx & 3;
            int grow = row0 + r;
            float4 vv = make_float4(0.f, 0.f, 0.f, 0.f);
            if (grow < M)
                vv = *reinterpret_cast<const float4*>(&A[grow * SDIM + k0 + q * 4]);
            As[q * 4 + 0][r] = vv.x; As[q * 4 + 1][r] = vv.y;
            As[q * 4 + 2][r] = vv.z; As[q * 4 + 3][r] = vv.w;
        }
        #pragma unroll
        for (int i = 0; i < 2; i++) {
            int idx = tid + 256 * i;
            int n = idx >> 2, q = idx & 3;
            float4 vv = *reinterpret_cast<const float4*>(&B[n * SDIM + k0 + q * 4]);
            Bs[q * 4 + 0][n] = vv.x; Bs[q * 4 + 1][n] = vv.y;
            Bs[q * 4 + 2][n] = vv.z; Bs[q * 4 + 3][n] = vv.w;
        }
        __syncthreads();
        #pragma unroll
        for (int kk = 0; kk < TK; kk++) {
            float4 aL = *reinterpret_cast<const float4*>(&As[kk][ty * 4]);
            float4 aH = *reinterpret_cast<const float4*>(&As[kk][ty * 4 + 64]);
            float4 bL = *reinterpret_cast<const float4*>(&Bs[kk][tx * 4]);
            float4 bH = *reinterpret_cast<const float4*>(&Bs[kk][tx * 4 + 64]);
            u64 a2[8];
            a2[0] = pack2(aL.x, aL.x); a2[1] = pack2(aL.y, aL.y);
            a2[2] = pack2(aL.z, aL.z); a2[3] = pack2(aL.w, aL.w);
            a2[4] = pack2(aH.x, aH.x); a2[5] = pack2(aH.y, aH.y);
            a2[6] = pack2(aH.z, aH.z); a2[7] = pack2(aH.w, aH.w);
            u64 b2[4];
            b2[0] = pack2(bL.x, bL.y); b2[1] = pack2(bL.z, bL.w);
            b2[2] = pack2(bH.x, bH.y); b2[3] = pack2(bH.z, bH.w);
            #pragma unroll
            for (int r = 0; r < 8; r++)
                #pragma unroll
                for (int c = 0; c < 4; c++)
                    fma2(acc[r][c], a2[r], b2[c]);
        }
        __syncthreads();
    }

    float4 bsL = make_float4(0.f, 0.f, 0.f, 0.f), bsH = bsL;
    if (bias) {
        bsL = *reinterpret_cast<const float4*>(&bias[tx * 4]);
        bsH = *reinterpret_cast<const float4*>(&bias[64 + tx * 4]);
    }
    #pragma unroll
    for (int r = 0; r < 8; r++) {
        int grow = row0 + ((r < 4) ? (ty * 4 + r) : (64 + ty * 4 + r - 4));
        if (grow >= M) continue;
        float2 p0 = unpack2(acc[r][0]), p1 = unpack2(acc[r][1]);
        float2 p2 = unpack2(acc[r][2]), p3 = unpack2(acc[r][3]);
        float4 lo = make_float4(p0.x + bsL.x, p0.y + bsL.y, p1.x + bsL.z, p1.y + bsL.w);
        float4 hi = make_float4(p2.x + bsH.x, p2.y + bsH.y, p3.x + bsH.z, p3.y + bsH.w);
        if (doRelu) {
            lo.x = fmaxf(lo.x, 0.f); lo.y = fmaxf(lo.y, 0.f);
            lo.z = fmaxf(lo.z, 0.f); lo.w = fmaxf(lo.w, 0.f);
            hi.x = fmaxf(hi.x, 0.f); hi.y = fmaxf(hi.y, 0.f);
            hi.z = fmaxf(hi.z, 0.f); hi.w = fmaxf(hi.w, 0.f);
        }
        if (toBf16) {
            uint2 uL = make_uint2(bf2(lo.x, lo.y), bf2(lo.z, lo.w));
            uint2 uH = make_uint2(bf2(hi.x, hi.y), bf2(hi.z, hi.w));
            *reinterpret_cast<uint2*>(&g_ub[grow * (SDIM / 2) + tx * 2]) = uL;
            *reinterpret_cast<uint2*>(&g_ub[grow * (SDIM / 2) + 32 + tx * 2]) = uH;
        } else {
            *reinterpret_cast<float4*>(&C[grow * SDIM + tx * 4]) = lo;
            *reinterpret_cast<float4*>(&C[grow * SDIM + 64 + tx * 4]) = hi;
        }
    }
}

// ---------------- MEGA1: wrv | fold_att | 3 GEMMs | count | logits ----------------
__global__ __launch_bounds__(256) void k_mega1(
    const float* __restrict__ xsrc, const float* __restrict__ xdst,
    const float* __restrict__ Wres, const float* __restrict__ Wpred1,
    const float* __restrict__ bpred1, const float* __restrict__ Wpred2,
    const float* __restrict__ bpred2, const float* __restrict__ Wself,
    const float* __restrict__ bself,
    const float* __restrict__ Wsrc, const float* __restrict__ attsrc,
    const float* __restrict__ Wdst, const float* __restrict__ attdst,
    const int* __restrict__ edst,
    float* __restrict__ dout,
    int Nsrc, int Ndst, int E, int nbg, int ncnt, int nrow8) {

    __shared__ float As[TK][TM + 4];
    __shared__ float Bs[TK][TN + 4];
    __shared__ float ws[4];

    int b = blockIdx.x;
    int t = threadIdx.x;

    // layout: [wrv 128][fold 4][gemm 3*nbg][count ncnt][logits 2*nrow8]
    if (b < SDIM) {
        // ---- wrv: one output row o = b ----
        int o = b;
        float* sh = &As[0][0];  // 128 floats
        if (t < SDIM) sh[t] = Wres[o * SDIM + t];
        __syncthreads();
        if (t < SDIM) {
            float s = 0.f;
            #pragma unroll 8
            for (int i = 0; i < SDIM; i++)
                s += sh[i] * Wpred2[i * SDIM + t];
            g_Wrv[o * SDIM + t] = s;
            float p = sh[t] * bpred2[t];
            p = warp_sum(p);
            if ((t & 31) == 0) ws[t >> 5] = p;
        }
        __syncthreads();
        if (t == 0) g_brv[o] = ws[0] + ws[1] + ws[2] + ws[3];
        return;
    }
    b -= SDIM;
    if (b < 4) {
        // ---- fold_att ----
        int side = b >> 1;
        const float* W   = side ? Wdst   : Wsrc;
        const float* att = side ? attdst : attsrc;
        float* out       = side ? g_Mdst : g_Msrc;
        int t2 = (b & 1) * 256 + t;          // 0..511
        int s = t2 >> 2, h = t2 & 3;
        float acc = 0.f;
        #pragma unroll 8
        for (int d = 0; d < DDIM; d++)
            acc += W[(h * DDIM + d) * SDIM + s] * att[h * DDIM + d];
        out[s * 4 + h] = acc;
        return;
    }
    b -= 4;
    if (b < 3 * nbg) {
        int j = b / nbg, bx = b % nbg;
        if (j == 0)      gemm_body(xsrc, Wres,   nullptr, nullptr, Nsrc, bx, 0, 1, As, Bs);
        else if (j == 1) gemm_body(xdst, Wpred1, bpred1,  g_t1,    Ndst, bx, 1, 0, As, Bs);
        else             gemm_body(xdst, Wself,  bself,   dout,    Ndst, bx, 0, 0, As, Bs);
        return;
    }
    b -= 3 * nbg;
    if (b < ncnt) {
        // ---- count: 4 edges per thread ----
        int i = b * 256 + t;
        int n4 = E >> 2;
        if (i < n4) {
            int4 d = reinterpret_cast<const int4*>(edst)[i];
            atomicAdd(&g_cnt[d.x], 1);
            atomicAdd(&g_cnt[d.y], 1);
            atomicAdd(&g_cnt[d.z], 1);
            atomicAdd(&g_cnt[d.w], 1);
        } else if (i == n4) {
            for (int j = n4 * 4; j < E; j++) atomicAdd(&g_cnt[edst[j]], 1);
        }
        return;
    }
    b -= ncnt;
    {
        // ---- logits: 8 rows per block (warp per row); float4 output ----
        int y = b / nrow8;
        int bx = b % nrow8;
        const float* x  = y ? xdst   : xsrc;
        const float* Mw = y ? g_Mdst : g_Msrc;
        float4* out     = y ? g_ad4  : g_as4;
        int N           = y ? Ndst   : Nsrc;
        int warp = t >> 5, lane = t & 31;
        int row = bx * 8 + warp;
        if (row >= N) return;
        const float* xr = x + row * SDIM;
        float p0 = 0, p1 = 0, p2 = 0, p3 = 0;
        #pragma unroll
        for (int k = lane; k < SDIM; k += 32) {
            float xv = __ldg(&xr[k]);
            p0 += xv * Mw[k * 4 + 0];
            p1 += xv * Mw[k * 4 + 1];
            p2 += xv * Mw[k * 4 + 2];
            p3 += xv * Mw[k * 4 + 3];
        }
        p0 = warp_sum(p0); p1 = warp_sum(p1); p2 = warp_sum(p2); p3 = warp_sum(p3);
        if (lane == 0)
            out[row] = make_float4(p0, p1, p2, p3);
    }
}

// ---------------- scan (prefix over degree counts) ----------------
__global__ void k_scan(int N) {
    __shared__ int sh[1024];
    int t = threadIdx.x;
    int per = (N + 1023) >> 10;
    int s = t * per, e = min(N, s + per);
    int tot = 0;
    for (int i = s; i < e; i++) tot += g_cnt[i];
    sh[t] = tot;
    __syncthreads();
    for (int o = 1; o < 1024; o <<= 1) {
        int v = (t >= o) ? sh[t - o] : 0;
        __syncthreads();
        sh[t] += v;
        __syncthreads();
    }
    int run = (t == 0) ? 0 : sh[t - 1];
    for (int i = s; i < e; i++) {
        g_off[i] = run;
        g_cur[i] = run;
        run += g_cnt[i];
    }
    if (t == 1023) g_off[N] = sh[1023];
}

// ---------------- MEGA2: v-GEMM | scatter ----------------
__global__ __launch_bounds__(256) void k_mega2(
    const int* __restrict__ esrc, const int* __restrict__ edst,
    int Ndst, int E, int nbg2, int ncnt) {

    __shared__ float As[TK][TM + 4];
    __shared__ float Bs[TK][TN + 4];

    int b = blockIdx.x;
    int t = threadIdx.x;
    if (b < nbg2) {
        gemm_body(g_t1, g_Wrv, g_brv, g_v, Ndst, b, 0, 0, As, Bs);
        return;
    }
    b -= nbg2;
    {
        int i = b * 256 + t;
        int n4 = E >> 2;
        if (i < n4) {
            int4 d = reinterpret_cast<const int4*>(edst)[i];
            int4 s = reinterpret_cast<const int4*>(esrc)[i];
            int p0 = atomicAdd(&g_cur[d.x], 1);
            int p1 = atomicAdd(&g_cur[d.y], 1);
            int p2 = atomicAdd(&g_cur[d.z], 1);
            int p3 = atomicAdd(&g_cur[d.w], 1);
            g_csr_src[p0] = s.x;
            g_csr_src[p1] = s.y;
            g_csr_src[p2] = s.z;
            g_csr_src[p3] = s.w;
        } else if (i == n4) {
            for (int j = n4 * 4; j < E; j++) {
                int p = atomicAdd(&g_cur[edst[j]], 1);
                g_csr_src[p] = esrc[j];
            }
        }
    }
}

// ---------------- edge aggregation: one block (128 thr) per dst node ----------------
// pass 1: all threads stride edges; ONE float4 logit load per edge (4 heads at once).
// pass 2: LDG.128 u loads (uint4 = 8 bf16 channels per thread).
#define CAP 512
__global__ __launch_bounds__(128) void k_edge(float* __restrict__ dout) {
    __shared__ int    sh_src[CAP];
    __shared__ float  sh_ex[4][CAP];
    __shared__ float  sh_denom[4];
    __shared__ float  wsum[4][4];   // [warp][head]
    __shared__ float  red[8][SDIM + 4];

    int d = blockIdx.x;
    int t = threadIdx.x;
    int warp = t >> 5, lane = t & 31;
    int start = g_off[d], end = g_off[d + 1];
    int n = end - start;
    float4 ad = g_ad4[d];

    // pass 1: each thread owns edges t, t+128, ...; 1 scattered LDG.128 per edge
    float d0 = 0.f, d1 = 0.f, d2 = 0.f, d3 = 0.f;
    for (int i = t; i < n; i += 128) {
        int src = g_csr_src[start + i];
        float4 a = __ldg(&g_as4[src]);
        float e0 = lrelu_exp(a.x + ad.x);
        float e1 = lrelu_exp(a.y + ad.y);
        float e2 = lrelu_exp(a.z + ad.z);
        float e3 = lrelu_exp(a.w + ad.w);
        if (i < CAP) {
            sh_src[i] = src;
            sh_ex[0][i] = e0; sh_ex[1][i] = e1;
            sh_ex[2][i] = e2; sh_ex[3][i] = e3;
        }
        d0 += e0; d1 += e1; d2 += e2; d3 += e3;
    }
    d0 = warp_sum(d0); d1 = warp_sum(d1); d2 = warp_sum(d2); d3 = warp_sum(d3);
    if (lane == 0) {
        wsum[warp][0] = d0; wsum[warp][1] = d1;
        wsum[warp][2] = d2; wsum[warp][3] = d3;
    }
    __syncthreads();
    if (t < 4)
        sh_denom[t] = wsum[0][t] + wsum[1][t] + wsum[2][t] + wsum[3][t];
    __syncthreads();

    // pass 2: 16 channel-groups (8 ch each) x 8 edge-slots; uint4 (16B) u loads
    int p = t & 15, slot = t >> 4;
    int h2 = p >> 2;
    float acc[8];
    #pragma unroll
    for (int j = 0; j < 8; j++) acc[j] = 0.f;

    int ncap = n < CAP ? n : CAP;
    #pragma unroll 4
    for (int i = slot; i < ncap; i += 8) {
        int src = sh_src[i];
        float w = sh_ex[h2][i];
        uint4 uv = __ldg(reinterpret_cast<const uint4*>(&g_ub[src * (SDIM / 2) + p * 4]));
        acc[0] += w * __uint_as_float(uv.x << 16);
        acc[1] += w * __uint_as_float(uv.x & 0xffff0000u);
        acc[2] += w * __uint_as_float(uv.y << 16);
        acc[3] += w * __uint_as_float(uv.y & 0xffff0000u);
        acc[4] += w * __uint_as_float(uv.z << 16);
        acc[5] += w * __uint_as_float(uv.z & 0xffff0000u);
        acc[6] += w * __uint_as_float(uv.w << 16);
        acc[7] += w * __uint_as_float(uv.w & 0xffff0000u);
    }
    if (n > CAP) {
        const float* gas = reinterpret_cast<const float*>(g_as4);
        float adh2 = reinterpret_cast<const float*>(&ad)[h2];
        for (int j = CAP + slot; j < n; j += 8) {
            int src = g_csr_src[start + j];
            float w = lrelu_exp(gas[src * 4 + h2] + adh2);
            uint4 uv = __ldg(reinterpret_cast<const uint4*>(&g_ub[src * (SDIM / 2) + p * 4]));
            acc[0] += w * __uint_as_float(uv.x << 16);
            acc[1] += w * __uint_as_float(uv.x & 0xffff0000u);
            acc[2] += w * __uint_as_float(uv.y << 16);
            acc[3] += w * __uint_as_float(uv.y & 0xffff0000u);
            acc[4] += w * __uint_as_float(uv.z << 16);
            acc[5] += w * __uint_as_float(uv.z & 0xffff0000u);
            acc[6] += w * __uint_as_float(uv.w << 16);
            acc[7] += w * __uint_as_float(uv.w & 0xffff0000u);
        }
    }
    #pragma unroll
    for (int j = 0; j < 8; j++) red[slot][p * 8 + j] = acc[j];
    __syncthreads();

    // final: thread t owns channel c=t
    int c = t;
    float a = 0.f;
    #pragma unroll
    for (int s = 0; s < 8; s++) a += red[s][c];
    float denom = sh_denom[c >> 5];
    float inv = 1.f / (denom + 1e-16f);
    float sumw = denom * inv;
    dout[d * SDIM + c] = dout[d * SDIM + c] + a * inv - g_v[d * SDIM + c] * sumw;
}

// ---------------- launch: 5-node single-stream chain ----------------
extern "C" void kernel_launch(void* const* d_in, const int* in_sizes, int n_in,
                              void* d_out, int out_size) {
    const float* x_src   = (const float*)d_in[0];
    const float* x_dst   = (const float*)d_in[1];
    const float* W_pred1 = (const float*)d_in[2];
    const float* b_pred1 = (const float*)d_in[3];
    const float* W_pred2 = (const float*)d_in[4];
    const float* b_pred2 = (const float*)d_in[5];
    const float* W_res   = (const float*)d_in[6];
    const float* W_src   = (const float*)d_in[7];
    const float* W_dst   = (const float*)d_in[8];
    const float* att_src = (const float*)d_in[9];
    const float* att_dst = (const float*)d_in[10];
    const float* W_self  = (const float*)d_in[11];
    const float* b_self  = (const float*)d_in[12];
    const int*   e_src   = (const int*)d_in[13];
    const int*   e_dst   = (const int*)d_in[14];
    float* out = (float*)d_out;

    int Nsrc = in_sizes[0] / SDIM;
    int Ndst = in_sizes[1] / SDIM;
    int E    = in_sizes[13];
    int maxN = Nsrc > Ndst ? Nsrc : Ndst;

    void* cnt_ptr = nullptr;
    cudaGetSymbolAddress(&cnt_ptr, g_cnt);

    int nbg   = (maxN + TM - 1) / TM;
    int nbg2  = (Ndst + TM - 1) / TM;
    int n4    = E >> 2;
    int ncnt  = (n4 + 1 + 255) / 256;
    int nrow8 = (maxN + 7) / 8;
    int grid1 = SDIM + 4 + 3 * nbg + ncnt + 2 * nrow8;
    int grid2 = nbg2 + ncnt;

    cudaMemsetAsync(cnt_ptr, 0, (Ndst + 1) * sizeof(int), 0);
    k_mega1<<<grid1, 256>>>(x_src, x_dst, W_res, W_pred1, b_pred1, W_pred2, b_pred2,
                            W_self, b_self, W_src, att_src, W_dst, att_dst,
                            e_dst, out, Nsrc, Ndst, E, nbg, ncnt, nrow8);
    k_scan<<<1, 1024>>>(Ndst);
    k_mega2<<<grid2, 256>>>(e_src, e_dst, Ndst, E, nbg2, ncnt);
    k_edge<<<Ndst, 128>>>(out);
}